// round 2
// baseline (speedup 1.0000x reference)
#include <cuda_runtime.h>
#include <math.h>

// ---------------- problem constants ----------------
#define kN    16
#define kC    80
#define kH    160
#define kW    160
#define kHW   (kH * kW)          // 25600
#define kCHW  (kC * kHW)         // 2048000
#define kPreK 1000
#define kPostK 200
#define kBins 65536
#define kCandCap (1 << 20)       // per-image candidate capacity (actual ~300k)
#define kGathCap 4096

#define kLogitThresh (-2.9444389791664403f)   // log(0.05/0.95)
#define kClipDWH 4.135166556742356f           // log(1000/16)
#define kImgMax  1279.0f
#define kOffScale 1281.0f                     // IMG + 1
#define kNmsThr  0.8f

// ---------------- device scratch (static; no allocation) ----------------
__device__ unsigned long long g_cand[kN][kCandCap];
__device__ unsigned int       g_hist[kN][kBins];
__device__ int                g_cnt[kN];
__device__ float              g_ctr[kN * kHW];   // sigmoid(centerness)

// ---------------- all-FMA sigmoid (no MUFU) ----------------
__device__ __forceinline__ float softexp(float x) {      // exp(x), |x|<20, ~1e-7 rel
    float z = x * 1.44269504088896340736f;
    float k = rintf(z);
    float r = (z - k) * 0.69314718055994530942f;          // |r| <= 0.3466
    float p = 1.0f / 5040.0f;
    p = fmaf(p, r, 1.0f / 720.0f);
    p = fmaf(p, r, 1.0f / 120.0f);
    p = fmaf(p, r, 1.0f / 24.0f);
    p = fmaf(p, r, 1.0f / 6.0f);
    p = fmaf(p, r, 0.5f);
    p = fmaf(p, r, 1.0f);
    p = fmaf(p, r, 1.0f);
    int ki = (int)k;
    float sc = __int_as_float((unsigned)(ki + 127) << 23);
    return p * sc;
}
__device__ __forceinline__ float fastrcp(float d) {       // 1/d, d in (1, ~500)
    float r = __uint_as_float(0x7EF311C3u - __float_as_uint(d));
    r = r * fmaf(-d, r, 2.0f);
    r = r * fmaf(-d, r, 2.0f);
    r = fmaf(r, fmaf(-d, r, 1.0f), r);                    // final refined step
    return r;
}
__device__ __forceinline__ float fsigmoid(float x) {
    return fastrcp(1.0f + softexp(-x));
}

// ---------------- kernel 0: reset scratch + ctr sigmoid table ----------------
__global__ void k_init(const float* __restrict__ ctr) {
    int t = blockIdx.x * blockDim.x + threadIdx.x;        // 4096*256 = 1,048,576 = kN*kBins
    ((unsigned int*)g_hist)[t] = 0u;
    if (t < kN * kHW) g_ctr[t] = fsigmoid(ctr[t]);
    if (t < kN) g_cnt[t] = 0;
}

// ---------------- kernel 1: fused threshold + score + histogram + compact ----------------
// key: high32 = score bits (positive f32, monotone), low32 = ~idx (desc => idx asc ties)
__global__ __launch_bounds__(256) void k_pass(const float* __restrict__ cls) {
    int t = blockIdx.x * blockDim.x + threadIdx.x;
    int p = t * 4;
    int n  = p / kCHW;
    int r  = p - n * kCHW;
    int c  = r / kHW;
    int hw = r - c * kHW;                                  // 4-chunk never crosses c

    float4 v = *(const float4*)(cls + p);
    float vals[4] = {v.x, v.y, v.z, v.w};
    bool pass[4];
    bool any = false;
#pragma unroll
    for (int k = 0; k < 4; k++) { pass[k] = vals[k] > kLogitThresh; any |= pass[k]; }

    unsigned long long lk[4];
    int m = 0;
    if (any) {
        float4 ct = *(const float4*)(g_ctr + n * kHW + hw);
        float cts[4] = {ct.x, ct.y, ct.z, ct.w};
#pragma unroll
        for (int k = 0; k < 4; k++) {
            if (pass[k]) {
                float pr = fsigmoid(vals[k]);
                float s  = pr * cts[k];
                unsigned sb = __float_as_uint(s);
                atomicAdd(&g_hist[n][sb >> 14], 1u);
                unsigned idx = (unsigned)((hw + k) * kC + c);
                lk[m++] = ((unsigned long long)sb << 32) | (unsigned)(~idx);
            }
        }
    }
    // warp-aggregated append (whole warp same image: 128 | kCHW)
    unsigned lane = threadIdx.x & 31;
    int incl = m;
#pragma unroll
    for (int d = 1; d < 32; d <<= 1) {
        int vv = __shfl_up_sync(0xffffffffu, incl, d);
        if (lane >= d) incl += vv;
    }
    int total = __shfl_sync(0xffffffffu, incl, 31);
    int base = 0;
    if (lane == 31 && total > 0) base = atomicAdd(&g_cnt[n], total);
    base = __shfl_sync(0xffffffffu, base, 31);
    int off = base + incl - m;
#pragma unroll
    for (int k = 0; k < 4; k++)
        if (k < m && off + k < kCandCap) g_cand[n][off + k] = lk[k];
}

// ---------------- kernel 2: per-image select + sort + decode + NMS + output ----------------
struct Post { float bx[kPreK][4]; float sc[kPreK]; };     // 20 KB
union Scratch {
    unsigned           csum[1024];                        // 4 KB  (phase 0)
    unsigned long long keys[kGathCap];                    // 32 KB (phases 1-2)
    Post               post;                              // 20 KB (phases 3+)
};

__global__ __launch_bounds__(1024) void k_select(const float* __restrict__ reg,
                                                 const float* __restrict__ anc,
                                                 float* __restrict__ out) {
    int n = blockIdx.x, t = threadIdx.x;
    __shared__ Scratch u;
    __shared__ unsigned short lab[kPreK];
    __shared__ unsigned char  keep_s[kPreK];
    __shared__ int keptList[kPostK];
    __shared__ int sh_B, sh_gcnt, sh_nv;

    // ---- phase 0: cutoff bin via parallel suffix scan over 64k-bin histogram ----
    const unsigned* __restrict__ h = g_hist[n];
    {
        const uint4* h4 = (const uint4*)(h + t * 64);
        unsigned s = 0;
#pragma unroll
        for (int q = 0; q < 16; q++) { uint4 w = h4[q]; s += w.x + w.y + w.z + w.w; }
        u.csum[t] = s;
    }
    if (t == 0) { sh_gcnt = 0; sh_nv = 0; }
    __syncthreads();
    for (int d = 1; d < 1024; d <<= 1) {                  // suffix inclusive scan
        unsigned v = (t + d < 1024) ? u.csum[t + d] : 0u;
        __syncthreads();
        u.csum[t] += v;
        __syncthreads();
    }
    {
        unsigned St = u.csum[t];
        unsigned Sn = (t < 1023) ? u.csum[t + 1] : 0u;
        if (St >= (unsigned)kPreK && Sn < (unsigned)kPreK) {
            // refine within this 64-bin chunk, register-resident (MLP loads)
            unsigned vb[64];
            const uint4* hp = (const uint4*)(h + t * 64);
#pragma unroll
            for (int q = 0; q < 16; q++) {
                uint4 w = hp[q];
                vb[q * 4 + 0] = w.x; vb[q * 4 + 1] = w.y;
                vb[q * 4 + 2] = w.z; vb[q * 4 + 3] = w.w;
            }
            unsigned cum = Sn; int B = t * 64;
#pragma unroll
            for (int b = 63; b >= 0; b--) {
                cum += vb[b];
                if (cum >= (unsigned)kPreK) { B = t * 64 + b; break; }
            }
            sh_B = B;
        }
        if (t == 0 && u.csum[0] < (unsigned)kPreK) sh_B = 0;
    }
    __syncthreads();
    int B = sh_B;
    __syncthreads();

    // ---- phase 1: gather candidates in bins >= B into smem ----
    for (int i = t; i < kGathCap; i += 1024) u.keys[i] = 0ull;
    __syncthreads();
    {
        int cnt = min(g_cnt[n], kCandCap);
        const unsigned long long* __restrict__ cand = g_cand[n];
#pragma unroll 4
        for (int j = t; j < cnt; j += 1024) {
            unsigned long long key = cand[j];
            if ((int)(key >> 46) >= B) {
                int pos = atomicAdd(&sh_gcnt, 1);
                if (pos < kGathCap) u.keys[pos] = key;
            }
        }
    }
    __syncthreads();
    int G = min(sh_gcnt, kGathCap);

    // ---- phase 2: bitonic sort (descending), dynamic size ----
    int S = 2; while (S < G) S <<= 1;
    for (int k = 2; k <= S; k <<= 1) {
        for (int j = k >> 1; j > 0; j >>= 1) {
            for (int i = t; i < S; i += 1024) {
                int l = i ^ j;
                if (l > i) {
                    unsigned long long a = u.keys[i], b = u.keys[l];
                    bool sw = ((i & k) == 0) ? (a < b) : (a > b);
                    if (sw) { u.keys[i] = b; u.keys[l] = a; }
                }
            }
            __syncthreads();
        }
    }

    // ---- phase 3: extract top-1000 into registers, then decode into smem ----
    unsigned long long mykey = (t < kPreK) ? u.keys[t] : 0ull;
    unsigned long long nxkey = (t < kPreK - 1) ? u.keys[t + 1] : 0ull;
    __syncthreads();                                       // keys -> post overlap barrier

    bool valid = false;
    float ox1 = 0, oy1 = 0, ox2 = 0, oy2 = 0, area_t = 0;
    bool kt = false;
    if (t < kPreK) {
        unsigned sb = (unsigned)(mykey >> 32);
        valid = (sb != 0u);
        keep_s[t] = valid ? 1 : 0;
        if (valid) {
            unsigned idx = ~(unsigned)mykey;
            int loc = idx / kC;
            int cl  = idx - loc * kC;
            float a0 = anc[loc * 4 + 0], a1 = anc[loc * 4 + 1];
            float a2 = anc[loc * 4 + 2], a3 = anc[loc * 4 + 3];
            float w = a2 - a0 + 1.0f, hh = a3 - a1 + 1.0f;
            float cx = a0 + 0.5f * w, cy = a1 + 0.5f * hh;
            float d0 = __ldg(reg + (n * 4 + 0) * kHW + loc);
            float d1 = __ldg(reg + (n * 4 + 1) * kHW + loc);
            float d2 = __ldg(reg + (n * 4 + 2) * kHW + loc);
            float d3 = __ldg(reg + (n * 4 + 3) * kHW + loc);
            float dx = d0 / 10.0f, dy = d1 / 10.0f;
            float dw = fminf(d2 / 5.0f, kClipDWH);
            float dh = fminf(d3 / 5.0f, kClipDWH);
            float pcx = dx * w + cx, pcy = dy * hh + cy;
            float pw = expf(dw) * w, ph = expf(dh) * hh;
            float x1 = pcx - 0.5f * pw, y1 = pcy - 0.5f * ph;
            float x2 = pcx + 0.5f * pw - 1.0f, y2 = pcy + 0.5f * ph - 1.0f;
            x1 = fminf(fmaxf(x1, 0.0f), kImgMax);
            y1 = fminf(fmaxf(y1, 0.0f), kImgMax);
            x2 = fminf(fmaxf(x2, 0.0f), kImgMax);
            y2 = fminf(fmaxf(y2, 0.0f), kImgMax);
            u.post.bx[t][0] = x1; u.post.bx[t][1] = y1;
            u.post.bx[t][2] = x2; u.post.bx[t][3] = y2;
            u.post.sc[t] = sqrtf(__uint_as_float(sb));
            lab[t] = (unsigned short)(cl + 1);
            float off = (float)(cl + 1) * kOffScale;       // same float math as reference
            ox1 = x1 + off; oy1 = y1 + off;
            ox2 = x2 + off; oy2 = y2 + off;
            area_t = fmaxf(ox2 - ox1, 0.0f) * fmaxf(oy2 - oy1, 0.0f);
            kt = true;
        }
        if (valid && (t == kPreK - 1 || (unsigned)(nxkey >> 32) == 0u)) sh_nv = t + 1;
    }
    __syncthreads();
    int nv = sh_nv;

    // ---- phase 4: greedy class-aware NMS (barrier only on kept iterations) ----
    int nk = 0;
    for (int i = 0; i < nv; i++) {
        if (nk >= kPostK) break;
        if (!keep_s[i]) continue;                          // uniform smem read
        float offi = (float)lab[i] * kOffScale;
        float bi0 = u.post.bx[i][0] + offi, bi1 = u.post.bx[i][1] + offi;
        float bi2 = u.post.bx[i][2] + offi, bi3 = u.post.bx[i][3] + offi;
        float ai  = fmaxf(bi2 - bi0, 0.0f) * fmaxf(bi3 - bi1, 0.0f);
        if (t == 0) keptList[nk] = i;
        if (t > i && kt) {
            float xx1 = fmaxf(bi0, ox1), yy1 = fmaxf(bi1, oy1);
            float xx2 = fminf(bi2, ox2), yy2 = fminf(bi3, oy2);
            float inter = fmaxf(xx2 - xx1, 0.0f) * fmaxf(yy2 - yy1, 0.0f);
            float iou = inter / fmaxf(ai + area_t - inter, 1e-9f);
            if (iou > kNmsThr) { kt = false; keep_s[t] = 0; }
        }
        nk++;
        __syncthreads();
    }
    __syncthreads();

    // ---- phase 5: output ----
    if (t < kPostK) {
        float* o = out + (n * kPostK + t) * 5;
        if (t < nk) {
            int i = keptList[t];
            o[0] = u.post.bx[i][0]; o[1] = u.post.bx[i][1];
            o[2] = u.post.bx[i][2]; o[3] = u.post.bx[i][3];
            o[4] = u.post.sc[i];
        } else {
            o[0] = 0.0f; o[1] = 0.0f; o[2] = 0.0f; o[3] = 0.0f; o[4] = 0.0f;
        }
    }
}

// ---------------- launcher ----------------
extern "C" void kernel_launch(void* const* d_in, const int* in_sizes, int n_in,
                              void* d_out, int out_size) {
    const float* cls = (const float*)d_in[0];   // [16,80,160,160]
    const float* reg = (const float*)d_in[1];   // [16,4,160,160]
    const float* ctr = (const float*)d_in[2];   // [16,1,160,160]
    const float* anc = (const float*)d_in[3];   // [25600,4]
    float* out = (float*)d_out;                 // [16,200,5]

    k_init<<<4096, 256>>>(ctr);
    k_pass<<<(kN * kCHW / 4) / 256, 256>>>(cls);   // 32000 blocks
    k_select<<<kN, 1024>>>(reg, anc, out);
}